// round 3
// baseline (speedup 1.0000x reference)
#include <cuda_runtime.h>

#define HH 1024
#define WW 1024
#define CC 8
#define NN 2
#define TH 32
#define TW 64
#define SROWS 64                 // TH + 32
#define SCOLS 96                 // TW + 32
#define SCH (SROWS*SCOLS)        // floats per channel plane
#define SWZ(o) ((o) ^ (((o) >> 3) & 0x70))

// ---- device-global scratch / accumulators ----
__device__ __align__(16) float g_scratch[NN*HH*WW];
__device__ unsigned int g_minbits;
__device__ unsigned int g_maxbits;
__device__ double g_sum;
__device__ unsigned long long g_cnt;

__global__ void init_k() {
    g_minbits = 0x7F800000u;
    g_maxbits = 0u;
    g_sum = 0.0;
    g_cnt = 0ull;
}

// Pass 1: gray diff + global min/max
__global__ void __launch_bounds__(256) mask_k(const float* __restrict__ mso,
                                              const float* __restrict__ pan) {
    int t = blockIdx.x * 256 + threadIdx.x;
    int p = t << 2;
    int n = p >> 20;
    int hw = p & 0xFFFFF;

    float4 acc = make_float4(0.f, 0.f, 0.f, 0.f);
#pragma unroll
    for (int c = 0; c < CC; c++) {
        float4 v = *(const float4*)&mso[((size_t)(n * CC + c) << 20) + hw];
        acc.x += v.x; acc.y += v.y; acc.z += v.z; acc.w += v.w;
    }
    float4 pv = *(const float4*)&pan[((size_t)n << 20) + hw];
    float4 g;
    g.x = fabsf(acc.x * 0.125f - pv.x);
    g.y = fabsf(acc.y * 0.125f - pv.y);
    g.z = fabsf(acc.z * 0.125f - pv.z);
    g.w = fabsf(acc.w * 0.125f - pv.w);
    *(float4*)&g_scratch[p] = g;

    float lmin = fminf(fminf(g.x, g.y), fminf(g.z, g.w));
    float lmax = fmaxf(fmaxf(g.x, g.y), fmaxf(g.z, g.w));
#pragma unroll
    for (int o = 16; o; o >>= 1) {
        lmin = fminf(lmin, __shfl_xor_sync(0xffffffffu, lmin, o));
        lmax = fmaxf(lmax, __shfl_xor_sync(0xffffffffu, lmax, o));
    }
    __shared__ float smn[8], smx[8];
    int lane = threadIdx.x & 31, wid = threadIdx.x >> 5;
    if (!lane) { smn[wid] = lmin; smx[wid] = lmax; }
    __syncthreads();
    if (threadIdx.x == 0) {
        float mn = smn[0], mx = smx[0];
#pragma unroll
        for (int i = 1; i < 8; i++) { mn = fminf(mn, smn[i]); mx = fmaxf(mx, smx[i]); }
        atomicMin(&g_minbits, __float_as_uint(mn));
        atomicMax(&g_maxbits, __float_as_uint(mx));
    }
}

// Pass 2: min-shift SAD, 8 px/thread, swizzled SMEM, sliding dj window
__global__ void __launch_bounds__(256, 1) main_k(const float* __restrict__ ms,
                                                 const float* __restrict__ tgt) {
    extern __shared__ char sm[];

    const int n  = blockIdx.z;
    const int h0 = blockIdx.y * TH;
    const int w0 = blockIdx.x * TW;
    const int tx = threadIdx.x;          // 0..7, 8 px each along w
    const int ty = threadIdx.y;          // 0..31
    const int tid = ty * 8 + tx;

    // ---- load target tile (reflect pad) into swizzled SMEM ----
    const int NV4 = CC * SROWS * (SCOLS / 4);     // 12288 float4
#pragma unroll 4
    for (int e4 = tid; e4 < NV4; e4 += 256) {
        int c   = e4 / (SROWS * (SCOLS / 4));
        int rem = e4 - c * SROWS * (SCOLS / 4);
        int r   = rem / (SCOLS / 4);
        int q   = rem - r * (SCOLS / 4);
        int gr = h0 + r - 16;
        gr = gr < 0 ? -gr : (gr >= HH ? 2 * HH - 2 - gr : gr);
        const float* src = tgt + (((size_t)n * CC + c) * HH + gr) * WW;
        int gcb = w0 + q * 4 - 16;
        float4 v;
        if (gcb >= 0 && gcb + 4 <= WW) {
            v = *(const float4*)(src + gcb);
        } else {
            int g0 = gcb,     g1 = gcb + 1, g2 = gcb + 2, g3 = gcb + 3;
            g0 = g0 < 0 ? -g0 : (g0 >= WW ? 2 * WW - 2 - g0 : g0);
            g1 = g1 < 0 ? -g1 : (g1 >= WW ? 2 * WW - 2 - g1 : g1);
            g2 = g2 < 0 ? -g2 : (g2 >= WW ? 2 * WW - 2 - g2 : g2);
            g3 = g3 < 0 ? -g3 : (g3 >= WW ? 2 * WW - 2 - g3 : g3);
            v = make_float4(src[g0], src[g1], src[g2], src[g3]);
        }
        int o = (c * SCH + r * SCOLS + q * 4) * 4;   // byte offset
        *(float4*)(sm + SWZ(o)) = v;
    }
    __syncthreads();

    const int h  = h0 + ty;
    const int wb = w0 + (tx << 3);

    // ms pixels: 8 channels x 8 px (two float4 groups)
    float4 ma[CC], mb[CC];
#pragma unroll
    for (int c = 0; c < CC; c++) {
        const float* p = &ms[(((size_t)n * CC + c) * HH + h) * WW + wb];
        ma[c] = *(const float4*)p;
        mb[c] = *(const float4*)(p + 4);
    }

    float minv[8];
#pragma unroll
    for (int i = 0; i < 8; i++) minv[i] = 3.4e38f;

#pragma unroll 1
    for (int di = 0; di < 9; di++) {
        float part[9][8];
#pragma unroll
        for (int dj = 0; dj < 9; dj++)
#pragma unroll
            for (int i = 0; i < 8; i++) part[dj][i] = 0.f;

        const int rowoff = (((ty + (di << 2)) * SCOLS) + (tx << 3)) << 2;  // bytes
#pragma unroll
        for (int c = 0; c < CC; c++) {
            const int base = c * (SCH * 4) + rowoff;
            float4 a = *(const float4*)(sm + SWZ(base));
            const float4 m0 = ma[c], m1 = mb[c];
#pragma unroll
            for (int dj = 0; dj < 9; dj++) {
                const int o = base + ((dj + 1) << 4);
                float4 b = *(const float4*)(sm + SWZ(o));
                part[dj][0] += fabsf(m0.x - a.x);
                part[dj][1] += fabsf(m0.y - a.y);
                part[dj][2] += fabsf(m0.z - a.z);
                part[dj][3] += fabsf(m0.w - a.w);
                part[dj][4] += fabsf(m1.x - b.x);
                part[dj][5] += fabsf(m1.y - b.y);
                part[dj][6] += fabsf(m1.z - b.z);
                part[dj][7] += fabsf(m1.w - b.w);
                a = b;
            }
        }
#pragma unroll
        for (int dj = 0; dj < 9; dj++)
#pragma unroll
            for (int i = 0; i < 8; i++)
                minv[i] = fminf(minv[i], part[dj][i]);
    }

    // ---- mask + reduction ----
    const float mn  = __uint_as_float(g_minbits);
    const float mx  = __uint_as_float(g_maxbits);
    const float thr = mn + (mx - mn) * (10.0f / 255.0f);

    const float* gp = &g_scratch[((size_t)n << 20) + h * WW + wb];
    float4 ga = *(const float4*)gp;
    float4 gb = *(const float4*)(gp + 4);
    float gv[8] = {ga.x, ga.y, ga.z, ga.w, gb.x, gb.y, gb.z, gb.w};

    float lsum = 0.f;
    int   lcnt = 0;
#pragma unroll
    for (int i = 0; i < 8; i++)
        if (gv[i] > thr) { lsum += minv[i]; lcnt++; }

#pragma unroll
    for (int o = 16; o; o >>= 1) {
        lsum += __shfl_xor_sync(0xffffffffu, lsum, o);
        lcnt += __shfl_xor_sync(0xffffffffu, lcnt, o);
    }
    __shared__ float wsum[8];
    __shared__ int   wcnt[8];
    int lane = tid & 31, wid = tid >> 5;
    if (!lane) { wsum[wid] = lsum; wcnt[wid] = lcnt; }
    __syncthreads();
    if (tid == 0) {
        double bs = 0.0; long long bc = 0;
#pragma unroll
        for (int i = 0; i < 8; i++) { bs += (double)wsum[i]; bc += wcnt[i]; }
        atomicAdd(&g_sum, bs);
        atomicAdd(&g_cnt, (unsigned long long)bc);
    }
}

__global__ void fin_k(float* out) {
    unsigned long long c = g_cnt;
    out[0] = (c > 0ull) ? (float)(g_sum / (double)c) : 0.0f;
}

extern "C" void kernel_launch(void* const* d_in, const int* in_sizes, int n_in,
                              void* d_out, int out_size) {
    const float* ms  = (const float*)d_in[0];
    const float* tgt = (const float*)d_in[1];
    const float* mso = (const float*)d_in[2];
    const float* pan = (const float*)d_in[3];
    float* out = (float*)d_out;

    const int smem = CC * SCH * (int)sizeof(float);   // 196608 B
    cudaFuncSetAttribute(main_k, cudaFuncAttributeMaxDynamicSharedMemorySize, smem);

    init_k<<<1, 1>>>();
    mask_k<<<(NN * HH * WW) / 4 / 256, 256>>>(mso, pan);
    dim3 grid(WW / TW, HH / TH, NN), blk(8, 32);
    main_k<<<grid, blk, smem>>>(ms, tgt);
    fin_k<<<1, 1>>>(out);
}

// round 4
// speedup vs baseline: 1.9837x; 1.9837x over previous
#include <cuda_runtime.h>

#define HH 1024
#define WW 1024
#define CC 8
#define NN 2
#define TH 32
#define TW 64
#define SROWS 64                 // TH + 32
#define SCOLS 96                 // TW + 32
#define SCH (SROWS*SCOLS)
#define NTHR 512

// ---- device-global scratch / accumulators ----
__device__ __align__(16) float g_scratch[NN*HH*WW];
__device__ unsigned int g_minbits;
__device__ unsigned int g_maxbits;
__device__ double g_sum;
__device__ unsigned long long g_cnt;

__global__ void init_k() {
    g_minbits = 0x7F800000u;
    g_maxbits = 0u;
    g_sum = 0.0;
    g_cnt = 0ull;
}

// Pass 1: gray diff + global min/max
__global__ void __launch_bounds__(256) mask_k(const float* __restrict__ mso,
                                              const float* __restrict__ pan) {
    int t = blockIdx.x * 256 + threadIdx.x;
    int p = t << 2;
    int n = p >> 20;
    int hw = p & 0xFFFFF;

    float4 acc = make_float4(0.f, 0.f, 0.f, 0.f);
#pragma unroll
    for (int c = 0; c < CC; c++) {
        float4 v = *(const float4*)&mso[((size_t)(n * CC + c) << 20) + hw];
        acc.x += v.x; acc.y += v.y; acc.z += v.z; acc.w += v.w;
    }
    float4 pv = *(const float4*)&pan[((size_t)n << 20) + hw];
    float4 g;
    g.x = fabsf(acc.x * 0.125f - pv.x);
    g.y = fabsf(acc.y * 0.125f - pv.y);
    g.z = fabsf(acc.z * 0.125f - pv.z);
    g.w = fabsf(acc.w * 0.125f - pv.w);
    *(float4*)&g_scratch[p] = g;

    float lmin = fminf(fminf(g.x, g.y), fminf(g.z, g.w));
    float lmax = fmaxf(fmaxf(g.x, g.y), fmaxf(g.z, g.w));
#pragma unroll
    for (int o = 16; o; o >>= 1) {
        lmin = fminf(lmin, __shfl_xor_sync(0xffffffffu, lmin, o));
        lmax = fmaxf(lmax, __shfl_xor_sync(0xffffffffu, lmax, o));
    }
    __shared__ float smn[8], smx[8];
    int lane = threadIdx.x & 31, wid = threadIdx.x >> 5;
    if (!lane) { smn[wid] = lmin; smx[wid] = lmax; }
    __syncthreads();
    if (threadIdx.x == 0) {
        float mn = smn[0], mx = smx[0];
#pragma unroll
        for (int i = 1; i < 8; i++) { mn = fminf(mn, smn[i]); mx = fmaxf(mx, smx[i]); }
        atomicMin(&g_minbits, __float_as_uint(mn));
        atomicMax(&g_maxbits, __float_as_uint(mx));
    }
}

// Pass 2: min-shift SAD, 512 threads, 4 px/thread, linear SMEM
__global__ void __launch_bounds__(NTHR, 1) main_k(const float* __restrict__ ms,
                                                  const float* __restrict__ tgt) {
    extern __shared__ float sT[];   // [CC][SROWS][SCOLS]

    const int n  = blockIdx.z;
    const int h0 = blockIdx.y * TH;
    const int w0 = blockIdx.x * TW;
    const int tx = threadIdx.x;      // 0..15 -> 4 px each along w
    const int ty = threadIdx.y;      // 0..31
    const int tid = ty * 16 + tx;

    // ---- load target tile (reflect pad), vectorized ----
    const int CPL4 = SCOLS / 4;                // 24 float4 per row
    const int NV4  = CC * SROWS * CPL4;        // 12288 = 24 * 512
#pragma unroll
    for (int it = 0; it < NV4 / NTHR; it++) {
        int e4  = it * NTHR + tid;
        int c   = e4 / (SROWS * CPL4);
        int rem = e4 - c * (SROWS * CPL4);
        int r   = rem / CPL4;
        int q   = rem - r * CPL4;
        int gr = h0 + r - 16;
        gr = gr < 0 ? -gr : (gr >= HH ? 2 * HH - 2 - gr : gr);
        const float* src = tgt + (((size_t)n * CC + c) * HH + gr) * WW;
        int gcb = w0 + q * 4 - 16;
        float4 v;
        if (gcb >= 0 && gcb + 4 <= WW) {
            v = *(const float4*)(src + gcb);
        } else {
            int g0 = gcb, g1 = gcb + 1, g2 = gcb + 2, g3 = gcb + 3;
            g0 = g0 < 0 ? -g0 : (g0 >= WW ? 2 * WW - 2 - g0 : g0);
            g1 = g1 < 0 ? -g1 : (g1 >= WW ? 2 * WW - 2 - g1 : g1);
            g2 = g2 < 0 ? -g2 : (g2 >= WW ? 2 * WW - 2 - g2 : g2);
            g3 = g3 < 0 ? -g3 : (g3 >= WW ? 2 * WW - 2 - g3 : g3);
            v = make_float4(src[g0], src[g1], src[g2], src[g3]);
        }
        *(float4*)&sT[c * SCH + r * SCOLS + q * 4] = v;
    }
    __syncthreads();

    const int h     = h0 + ty;
    const int wbase = w0 + (tx << 2);

    // ms pixels: 8 channels x 4 px
    float4 msr[CC];
#pragma unroll
    for (int c = 0; c < CC; c++)
        msr[c] = *(const float4*)&ms[(((size_t)n * CC + c) * HH + h) * WW + wbase];

    float minv[4] = {3.4e38f, 3.4e38f, 3.4e38f, 3.4e38f};

#pragma unroll 1
    for (int di = 0; di < 9; di++) {
        float part[36];
#pragma unroll
        for (int i = 0; i < 36; i++) part[i] = 0.f;

        const int rb = (ty + (di << 2)) * SCOLS + (tx << 2);
#pragma unroll
        for (int c = 0; c < CC; c++) {
            const float* p = sT + c * SCH + rb;
            const float4 m = msr[c];
#pragma unroll
            for (int dj = 0; dj < 9; dj++) {
                float4 tv = *(const float4*)(p + (dj << 2));
                part[dj * 4 + 0] += fabsf(m.x - tv.x);
                part[dj * 4 + 1] += fabsf(m.y - tv.y);
                part[dj * 4 + 2] += fabsf(m.z - tv.z);
                part[dj * 4 + 3] += fabsf(m.w - tv.w);
            }
        }
#pragma unroll
        for (int dj = 0; dj < 9; dj++) {
            minv[0] = fminf(minv[0], part[dj * 4 + 0]);
            minv[1] = fminf(minv[1], part[dj * 4 + 1]);
            minv[2] = fminf(minv[2], part[dj * 4 + 2]);
            minv[3] = fminf(minv[3], part[dj * 4 + 3]);
        }
    }

    // ---- mask + reduction ----
    const float mn  = __uint_as_float(g_minbits);
    const float mx  = __uint_as_float(g_maxbits);
    const float thr = mn + (mx - mn) * (10.0f / 255.0f);

    float4 g = *(const float4*)&g_scratch[((size_t)n << 20) + h * WW + wbase];
    float lsum = 0.f;
    int   lcnt = 0;
    if (g.x > thr) { lsum += minv[0]; lcnt++; }
    if (g.y > thr) { lsum += minv[1]; lcnt++; }
    if (g.z > thr) { lsum += minv[2]; lcnt++; }
    if (g.w > thr) { lsum += minv[3]; lcnt++; }

#pragma unroll
    for (int o = 16; o; o >>= 1) {
        lsum += __shfl_xor_sync(0xffffffffu, lsum, o);
        lcnt += __shfl_xor_sync(0xffffffffu, lcnt, o);
    }
    __shared__ float wsum[16];
    __shared__ int   wcnt[16];
    int lane = tid & 31, wid = tid >> 5;
    if (!lane) { wsum[wid] = lsum; wcnt[wid] = lcnt; }
    __syncthreads();
    if (tid == 0) {
        double bs = 0.0; long long bc = 0;
#pragma unroll
        for (int i = 0; i < 16; i++) { bs += (double)wsum[i]; bc += wcnt[i]; }
        atomicAdd(&g_sum, bs);
        atomicAdd(&g_cnt, (unsigned long long)bc);
    }
}

__global__ void fin_k(float* out) {
    unsigned long long c = g_cnt;
    out[0] = (c > 0ull) ? (float)(g_sum / (double)c) : 0.0f;
}

extern "C" void kernel_launch(void* const* d_in, const int* in_sizes, int n_in,
                              void* d_out, int out_size) {
    const float* ms  = (const float*)d_in[0];
    const float* tgt = (const float*)d_in[1];
    const float* mso = (const float*)d_in[2];
    const float* pan = (const float*)d_in[3];
    float* out = (float*)d_out;

    const int smem = CC * SCH * (int)sizeof(float);   // 196608 B
    cudaFuncSetAttribute(main_k, cudaFuncAttributeMaxDynamicSharedMemorySize, smem);

    init_k<<<1, 1>>>();
    mask_k<<<(NN * HH * WW) / 4 / 256, 256>>>(mso, pan);
    dim3 grid(WW / TW, HH / TH, NN), blk(16, 32);
    main_k<<<grid, blk, smem>>>(ms, tgt);
    fin_k<<<1, 1>>>(out);
}